// round 11
// baseline (speedup 1.0000x reference)
#include <cuda_runtime.h>
#include <math.h>

// Problem constants
constexpr int B_ = 16, N_ = 4096, D_ = 64, O_ = 12, S_ = 32, M_ = 12, A_ = 32;
constexpr int NT = 128;                       // n-rows per block
constexpr float SCALE_ = 0.17677669529663687f; // 1/sqrt(A)
constexpr float ALPHA_ = 0.1f;
constexpr float TWO_PI = 6.283185307179586f;

using u64 = unsigned long long;

// ---- packed f32x2 helpers (sm_103a) ---------------------------------------
__device__ __forceinline__ u64 splat2(float x) {
    u64 r; asm("mov.b64 %0, {%1, %1};" : "=l"(r) : "f"(x)); return r;
}
__device__ __forceinline__ u64 pk2(float lo, float hi) {
    u64 r; asm("mov.b64 %0, {%1, %2};" : "=l"(r) : "f"(lo), "f"(hi)); return r;
}
__device__ __forceinline__ float2 unpk2(u64 v) {
    float2 f; asm("mov.b64 {%0, %1}, %2;" : "=f"(f.x), "=f"(f.y) : "l"(v)); return f;
}
__device__ __forceinline__ u64 ffma2(u64 a, u64 b, u64 c) {
    u64 d; asm("fma.rn.f32x2 %0, %1, %2, %3;" : "=l"(d) : "l"(a), "l"(b), "l"(c)); return d;
}

// Scratch (per (b,o) precomputed small tensors)
__device__ __align__(16) float g_keys[B_ * O_ * M_ * A_]; // [bo][m][a]  (pre-scaled by SCALE_)
__device__ __align__(16) float g_vals[B_ * O_ * M_ * D_]; // [bo][m][d]  (gated)
__device__ __align__(16) float g_qsk [B_ * O_ * M_];      // [bo][m] = qs . key_scaled[m]

// ---------------------------------------------------------------------------
// Prep: per (b,o) fourier tokens, gate (-> output), scaled keys, gated vals,
// folded scalar qsk[m] = (step_emb@WqS + bq) . (SCALE * key[m]).
// ---------------------------------------------------------------------------
__global__ void prep_kernel(const float* __restrict__ ts_out,
                            const float* __restrict__ step_emb,
                            const float* __restrict__ key_emb,
                            const float* __restrict__ val_emb,
                            const float* __restrict__ Wk,
                            const float* __restrict__ Wg,
                            const float* __restrict__ bg,
                            const float* __restrict__ Wq,
                            const float* __restrict__ bq,
                            float* __restrict__ out_gate)
{
    const int bo = blockIdx.x;
    const int t  = threadIdx.x;

    __shared__ float s_sin[M_], s_cos[M_], s_gate[M_], s_qs[A_], s_keys[M_ * A_];

    if (t < M_) {
        float phase = (t < 8) ? ts_out[bo * 2 + 0] : ts_out[bo * 2 + 1];
        int   k     = (t < 8) ? (t + 1) : (t - 7);
        float ang   = TWO_PI * phase * (float)k;
        float s, c;
        sincosf(ang, &s, &c);
        s_sin[t] = s;
        s_cos[t] = c;
        float gate = tanhf(fmaf(Wg[0], s, fmaf(Wg[1], c, bg[0])));
        s_gate[t] = gate;
        out_gate[bo * M_ + t] = gate;
    }
    if (t < A_) {
        float acc = bq[t];
        const float* se = step_emb + bo * S_;
        const float* w  = Wq + t * (D_ + S_) + D_;
        #pragma unroll
        for (int s = 0; s < S_; s++) acc = fmaf(se[s], w[s], acc);
        s_qs[t] = acc;
    }
    __syncthreads();

    // keys[m][a], pre-scaled by SCALE_
    for (int i = t; i < M_ * A_; i += blockDim.x) {
        int m = i / A_, a = i % A_;
        float v = fmaf(Wk[a * 2 + 0], s_sin[m], fmaf(Wk[a * 2 + 1], s_cos[m], key_emb[i]));
        v *= SCALE_;
        s_keys[i] = v;
        g_keys[bo * M_ * A_ + i] = v;
    }
    // gated vals[m][d]
    for (int i = t; i < M_ * D_; i += blockDim.x) {
        int m = i / D_;
        g_vals[bo * M_ * D_ + i] = s_gate[m] * val_emb[i];
    }
    __syncthreads();

    if (t < M_) {
        float acc = 0.f;
        #pragma unroll
        for (int a = 0; a < A_; a++) acc = fmaf(s_qs[a], s_keys[t * A_ + a], acc);
        g_qsk[bo * M_ + t] = acc;
    }
}

// ---------------------------------------------------------------------------
// Main: one block per (b, 128-row n-tile). qh computed once, reused for all O.
// f32x2 packed math throughout; vals hoisted to registers in the epilogue.
// ---------------------------------------------------------------------------
__global__ void __launch_bounds__(NT, 4)
main_kernel(const float* __restrict__ H,
            const float* __restrict__ Wq,
            float* __restrict__ outH,
            float* __restrict__ outAttn)
{
    extern __shared__ float4 sm4[];
    float4* Hs4   = sm4;               // [128][17] padded -> 2176 float4
    float4* Wq4   = Hs4 + NT * 17;     // [32][16]          -> 512
    float4* keys4 = Wq4 + 512;         // [12][8]           -> 96
    float4* vals4 = keys4 + 96;        // [12][16]          -> 192
    float*  attn_s = (float*)(vals4 + 192); // [128][12] contiguous (float4-friendly)
    float*  qsk_s  = attn_s + NT * 12;      // [12]

    const int t  = threadIdx.x;
    const int n0 = blockIdx.x * NT;
    const int b  = blockIdx.y;

    // Stage H tile (coalesced), padded stride 17 (conflict-free epilogue reads).
    const float4* Hg4 = (const float4*)(H + ((size_t)b * N_ + n0) * D_);
    for (int i = t; i < NT * 16; i += NT)
        Hs4[(i >> 4) * 17 + (i & 15)] = Hg4[i];

    // Stage Wq (first D columns) as [a][d4] float4.
    for (int i = t; i < A_ * 16; i += NT) {
        int a = i >> 4, d4 = i & 15;
        Wq4[i] = *(const float4*)(Wq + a * (D_ + S_) + d4 * 4);
    }
    __syncthreads();

    // qh[a] = H[row] . Wq[a,:D], accumulated over d-pairs with f32x2,
    // then reduced and repacked into a-pairs qh2[j] = (qh[2j], qh[2j+1]).
    u64 acc2[A_];
    #pragma unroll
    for (int a = 0; a < A_; a++) acc2[a] = 0ull;
    #pragma unroll 4
    for (int d4 = 0; d4 < 16; d4++) {
        ulonglong2 h2 = *reinterpret_cast<const ulonglong2*>(&Hs4[t * 17 + d4]);
        #pragma unroll
        for (int a = 0; a < A_; a++) {
            ulonglong2 w2 = *reinterpret_cast<const ulonglong2*>(&Wq4[a * 16 + d4]);
            acc2[a] = ffma2(h2.x, w2.x, acc2[a]);
            acc2[a] = ffma2(h2.y, w2.y, acc2[a]);
        }
    }
    u64 qh2[A_ / 2];
    #pragma unroll
    for (int j = 0; j < A_ / 2; j++) {
        float2 p = unpk2(acc2[2 * j]);
        float2 q = unpk2(acc2[2 * j + 1]);
        qh2[j] = pk2(p.x + p.y, q.x + q.y);
    }

    const int rbase = t >> 4;   // 0..7
    const int d4i   = t & 15;   // 0..15
    const u64 alpha2 = pk2(ALPHA_, ALPHA_);

    for (int o = 0; o < O_; o++) {
        const int bo = b * O_ + o;
        __syncthreads();  // previous iteration's readers of keys/vals/attn done

        const float4* gk4 = (const float4*)(g_keys + bo * M_ * A_);
        if (t < 96)  keys4[t] = gk4[t];
        const float4* gv4 = (const float4*)(g_vals + bo * M_ * D_);
        for (int i = t; i < 192; i += NT) vals4[i] = gv4[i];
        if (t < M_)  qsk_s[t] = g_qsk[bo * M_ + t];
        __syncthreads();

        // logits (f32x2 over a-pairs) + softmax in registers
        float lg[M_];
        #pragma unroll
        for (int m = 0; m < M_; m++) {
            u64 acc = 0ull;
            #pragma unroll
            for (int a4 = 0; a4 < 8; a4++) {
                ulonglong2 k2 = *reinterpret_cast<const ulonglong2*>(&keys4[m * 8 + a4]);
                acc = ffma2(qh2[2 * a4],     k2.x, acc);
                acc = ffma2(qh2[2 * a4 + 1], k2.y, acc);
            }
            float2 p = unpk2(acc);
            lg[m] = p.x + p.y + qsk_s[m];   // SCALE_ already folded into keys/qsk
        }
        float mx = lg[0];
        #pragma unroll
        for (int m = 1; m < M_; m++) mx = fmaxf(mx, lg[m]);
        float sum = 0.f;
        #pragma unroll
        for (int m = 0; m < M_; m++) { lg[m] = __expf(lg[m] - mx); sum += lg[m]; }
        float inv = 1.0f / sum;
        #pragma unroll
        for (int m = 0; m < M_; m++) lg[m] *= inv;

        // attn -> smem as 3 float4 (row stride 12 floats = 48B, 16B aligned)
        float4* arw = (float4*)(attn_s + t * 12);
        arw[0] = make_float4(lg[0], lg[1], lg[2],  lg[3]);
        arw[1] = make_float4(lg[4], lg[5], lg[6],  lg[7]);
        arw[2] = make_float4(lg[8], lg[9], lg[10], lg[11]);
        __syncthreads();

        // attn global write: smem layout == global layout -> straight float4 copy
        {
            float4* oa4 = (float4*)(outAttn + ((size_t)bo * N_ + n0) * M_);
            const float4* as4 = (const float4*)attn_s;
            #pragma unroll
            for (int k = 0; k < 3; k++) oa4[t + k * NT] = as4[t + k * NT];
        }

        // hoist this thread's gated vals (fixed d4i) into registers: 12 LDS.128
        u64 v2a[M_], v2b[M_];
        #pragma unroll
        for (int m = 0; m < M_; m++) {
            ulonglong2 vv = *reinterpret_cast<const ulonglong2*>(&vals4[m * 16 + d4i]);
            v2a[m] = vv.x;
            v2b[m] = vv.y;
        }

        // H_time epilogue: 16 rows per thread, f32x2 packed, coalesced STG.128
        float4* oh = (float4*)outH + ((size_t)bo * N_ + n0) * 16;
        #pragma unroll 1
        for (int it = 0; it < 16; it++) {
            int row = it * 8 + rbase;
            ulonglong2 h2 = *reinterpret_cast<const ulonglong2*>(&Hs4[row * 17 + d4i]);
            const float4* arow = (const float4*)(attn_s + row * 12);
            float4 a0 = arow[0], a1 = arow[1], a2 = arow[2];
            float am[M_] = {a0.x, a0.y, a0.z, a0.w,
                            a1.x, a1.y, a1.z, a1.w,
                            a2.x, a2.y, a2.z, a2.w};
            u64 acca = 0ull, accb = 0ull;
            #pragma unroll
            for (int m = 0; m < M_; m++) {
                u64 s = splat2(am[m]);
                acca = ffma2(s, v2a[m], acca);
                accb = ffma2(s, v2b[m], accb);
            }
            ulonglong2 r;
            r.x = ffma2(alpha2, acca, h2.x);
            r.y = ffma2(alpha2, accb, h2.y);
            *reinterpret_cast<ulonglong2*>(&oh[(size_t)row * 16 + d4i]) = r;
        }
    }
}

// ---------------------------------------------------------------------------
extern "C" void kernel_launch(void* const* d_in, const int* in_sizes, int n_in,
                              void* d_out, int out_size)
{
    const float* H        = (const float*)d_in[0];
    const float* ts_out   = (const float*)d_in[1];
    const float* step_emb = (const float*)d_in[2];
    const float* key_emb  = (const float*)d_in[3];
    const float* val_emb  = (const float*)d_in[4];
    const float* Wk       = (const float*)d_in[5];
    const float* Wg       = (const float*)d_in[6];
    const float* bg       = (const float*)d_in[7];
    const float* Wq       = (const float*)d_in[8];
    const float* bq       = (const float*)d_in[9];

    float* out     = (float*)d_out;
    float* outH    = out;                                   // [B,O,N,D]
    float* outAttn = out + (size_t)B_ * O_ * N_ * D_;       // [B,O,N,M]
    float* outGate = outAttn + (size_t)B_ * O_ * N_ * M_;   // [B,O,M]

    prep_kernel<<<B_ * O_, 128>>>(ts_out, step_emb, key_emb, val_emb,
                                  Wk, Wg, bg, Wq, bq, outGate);

    const int smem = (NT * 17 + 512 + 96 + 192) * (int)sizeof(float4)
                   + (NT * 12 + 12) * (int)sizeof(float);   // 53,808 B
    cudaFuncSetAttribute(main_kernel, cudaFuncAttributeMaxDynamicSharedMemorySize, smem);
    dim3 grid(N_ / NT, B_);
    main_kernel<<<grid, NT, smem>>>(H, Wq, outH, outAttn);
}

// round 12
// speedup vs baseline: 1.0003x; 1.0003x over previous
#include <cuda_runtime.h>
#include <math.h>

// Problem constants
constexpr int B_ = 16, N_ = 4096, D_ = 64, O_ = 12, S_ = 32, M_ = 12, A_ = 32;
constexpr int NT = 128;                       // n-rows per block
constexpr float SCALE_ = 0.17677669529663687f; // 1/sqrt(A)
constexpr float ALPHA_ = 0.1f;
constexpr float TWO_PI = 6.283185307179586f;

using u64 = unsigned long long;

// ---- packed f32x2 helpers (sm_103a) ---------------------------------------
__device__ __forceinline__ u64 splat2(float x) {
    u64 r; asm("mov.b64 %0, {%1, %1};" : "=l"(r) : "f"(x)); return r;
}
__device__ __forceinline__ u64 pk2(float lo, float hi) {
    u64 r; asm("mov.b64 %0, {%1, %2};" : "=l"(r) : "f"(lo), "f"(hi)); return r;
}
__device__ __forceinline__ float2 unpk2(u64 v) {
    float2 f; asm("mov.b64 {%0, %1}, %2;" : "=f"(f.x), "=f"(f.y) : "l"(v)); return f;
}
__device__ __forceinline__ u64 ffma2(u64 a, u64 b, u64 c) {
    u64 d; asm("fma.rn.f32x2 %0, %1, %2, %3;" : "=l"(d) : "l"(a), "l"(b), "l"(c)); return d;
}

// Scratch (per (b,o) precomputed small tensors)
__device__ __align__(16) float g_keys[B_ * O_ * M_ * A_]; // [bo][m][a]  (pre-scaled by SCALE_)
__device__ __align__(16) float g_vals[B_ * O_ * M_ * D_]; // [bo][m][d]  (gated)
__device__ __align__(16) float g_qsk [B_ * O_ * M_];      // [bo][m] = qs . key_scaled[m]

// ---------------------------------------------------------------------------
// Prep: per (b,o) fourier tokens, gate (-> output), scaled keys, gated vals,
// folded scalar qsk[m] = (step_emb@WqS + bq) . (SCALE * key[m]).
// ---------------------------------------------------------------------------
__global__ void prep_kernel(const float* __restrict__ ts_out,
                            const float* __restrict__ step_emb,
                            const float* __restrict__ key_emb,
                            const float* __restrict__ val_emb,
                            const float* __restrict__ Wk,
                            const float* __restrict__ Wg,
                            const float* __restrict__ bg,
                            const float* __restrict__ Wq,
                            const float* __restrict__ bq,
                            float* __restrict__ out_gate)
{
    const int bo = blockIdx.x;
    const int t  = threadIdx.x;

    __shared__ float s_sin[M_], s_cos[M_], s_gate[M_], s_qs[A_], s_keys[M_ * A_];

    if (t < M_) {
        float phase = (t < 8) ? ts_out[bo * 2 + 0] : ts_out[bo * 2 + 1];
        int   k     = (t < 8) ? (t + 1) : (t - 7);
        float ang   = TWO_PI * phase * (float)k;
        float s, c;
        sincosf(ang, &s, &c);
        s_sin[t] = s;
        s_cos[t] = c;
        float gate = tanhf(fmaf(Wg[0], s, fmaf(Wg[1], c, bg[0])));
        s_gate[t] = gate;
        out_gate[bo * M_ + t] = gate;
    }
    if (t < A_) {
        float acc = bq[t];
        const float* se = step_emb + bo * S_;
        const float* w  = Wq + t * (D_ + S_) + D_;
        #pragma unroll
        for (int s = 0; s < S_; s++) acc = fmaf(se[s], w[s], acc);
        s_qs[t] = acc;
    }
    __syncthreads();

    // keys[m][a], pre-scaled by SCALE_
    for (int i = t; i < M_ * A_; i += blockDim.x) {
        int m = i / A_, a = i % A_;
        float v = fmaf(Wk[a * 2 + 0], s_sin[m], fmaf(Wk[a * 2 + 1], s_cos[m], key_emb[i]));
        v *= SCALE_;
        s_keys[i] = v;
        g_keys[bo * M_ * A_ + i] = v;
    }
    // gated vals[m][d]
    for (int i = t; i < M_ * D_; i += blockDim.x) {
        int m = i / D_;
        g_vals[bo * M_ * D_ + i] = s_gate[m] * val_emb[i];
    }
    __syncthreads();

    if (t < M_) {
        float acc = 0.f;
        #pragma unroll
        for (int a = 0; a < A_; a++) acc = fmaf(s_qs[a], s_keys[t * A_ + a], acc);
        g_qsk[bo * M_ + t] = acc;
    }
}

// ---------------------------------------------------------------------------
// Main: one block per (b, 128-row n-tile). qh computed once, reused for all O.
// f32x2 packed math throughout; vals hoisted to registers in the epilogue.
// ---------------------------------------------------------------------------
__global__ void __launch_bounds__(NT, 4)
main_kernel(const float* __restrict__ H,
            const float* __restrict__ Wq,
            float* __restrict__ outH,
            float* __restrict__ outAttn)
{
    extern __shared__ float4 sm4[];
    float4* Hs4   = sm4;               // [128][17] padded -> 2176 float4
    float4* Wq4   = Hs4 + NT * 17;     // [32][16]          -> 512
    float4* keys4 = Wq4 + 512;         // [12][8]           -> 96
    float4* vals4 = keys4 + 96;        // [12][16]          -> 192
    float*  attn_s = (float*)(vals4 + 192); // [128][12] contiguous (float4-friendly)
    float*  qsk_s  = attn_s + NT * 12;      // [12]

    const int t  = threadIdx.x;
    const int n0 = blockIdx.x * NT;
    const int b  = blockIdx.y;

    // Stage H tile (coalesced), padded stride 17 (conflict-free epilogue reads).
    const float4* Hg4 = (const float4*)(H + ((size_t)b * N_ + n0) * D_);
    for (int i = t; i < NT * 16; i += NT)
        Hs4[(i >> 4) * 17 + (i & 15)] = Hg4[i];

    // Stage Wq (first D columns) as [a][d4] float4.
    for (int i = t; i < A_ * 16; i += NT) {
        int a = i >> 4, d4 = i & 15;
        Wq4[i] = *(const float4*)(Wq + a * (D_ + S_) + d4 * 4);
    }
    __syncthreads();

    // qh[a] = H[row] . Wq[a,:D], accumulated over d-pairs with f32x2,
    // then reduced and repacked into a-pairs qh2[j] = (qh[2j], qh[2j+1]).
    u64 acc2[A_];
    #pragma unroll
    for (int a = 0; a < A_; a++) acc2[a] = 0ull;
    #pragma unroll 4
    for (int d4 = 0; d4 < 16; d4++) {
        ulonglong2 h2 = *reinterpret_cast<const ulonglong2*>(&Hs4[t * 17 + d4]);
        #pragma unroll
        for (int a = 0; a < A_; a++) {
            ulonglong2 w2 = *reinterpret_cast<const ulonglong2*>(&Wq4[a * 16 + d4]);
            acc2[a] = ffma2(h2.x, w2.x, acc2[a]);
            acc2[a] = ffma2(h2.y, w2.y, acc2[a]);
        }
    }
    u64 qh2[A_ / 2];
    #pragma unroll
    for (int j = 0; j < A_ / 2; j++) {
        float2 p = unpk2(acc2[2 * j]);
        float2 q = unpk2(acc2[2 * j + 1]);
        qh2[j] = pk2(p.x + p.y, q.x + q.y);
    }

    const int rbase = t >> 4;   // 0..7
    const int d4i   = t & 15;   // 0..15
    const u64 alpha2 = pk2(ALPHA_, ALPHA_);

    for (int o = 0; o < O_; o++) {
        const int bo = b * O_ + o;
        __syncthreads();  // previous iteration's readers of keys/vals/attn done

        const float4* gk4 = (const float4*)(g_keys + bo * M_ * A_);
        if (t < 96)  keys4[t] = gk4[t];
        const float4* gv4 = (const float4*)(g_vals + bo * M_ * D_);
        for (int i = t; i < 192; i += NT) vals4[i] = gv4[i];
        if (t < M_)  qsk_s[t] = g_qsk[bo * M_ + t];
        __syncthreads();

        // logits (f32x2 over a-pairs) + softmax in registers
        float lg[M_];
        #pragma unroll
        for (int m = 0; m < M_; m++) {
            u64 acc = 0ull;
            #pragma unroll
            for (int a4 = 0; a4 < 8; a4++) {
                ulonglong2 k2 = *reinterpret_cast<const ulonglong2*>(&keys4[m * 8 + a4]);
                acc = ffma2(qh2[2 * a4],     k2.x, acc);
                acc = ffma2(qh2[2 * a4 + 1], k2.y, acc);
            }
            float2 p = unpk2(acc);
            lg[m] = p.x + p.y + qsk_s[m];   // SCALE_ already folded into keys/qsk
        }
        float mx = lg[0];
        #pragma unroll
        for (int m = 1; m < M_; m++) mx = fmaxf(mx, lg[m]);
        float sum = 0.f;
        #pragma unroll
        for (int m = 0; m < M_; m++) { lg[m] = __expf(lg[m] - mx); sum += lg[m]; }
        float inv = 1.0f / sum;
        #pragma unroll
        for (int m = 0; m < M_; m++) lg[m] *= inv;

        // attn -> smem as 3 float4 (row stride 12 floats = 48B, 16B aligned)
        float4* arw = (float4*)(attn_s + t * 12);
        arw[0] = make_float4(lg[0], lg[1], lg[2],  lg[3]);
        arw[1] = make_float4(lg[4], lg[5], lg[6],  lg[7]);
        arw[2] = make_float4(lg[8], lg[9], lg[10], lg[11]);
        __syncthreads();

        // attn global write: smem layout == global layout -> straight float4 copy
        {
            float4* oa4 = (float4*)(outAttn + ((size_t)bo * N_ + n0) * M_);
            const float4* as4 = (const float4*)attn_s;
            #pragma unroll
            for (int k = 0; k < 3; k++) oa4[t + k * NT] = as4[t + k * NT];
        }

        // hoist this thread's gated vals (fixed d4i) into registers: 12 LDS.128
        u64 v2a[M_], v2b[M_];
        #pragma unroll
        for (int m = 0; m < M_; m++) {
            ulonglong2 vv = *reinterpret_cast<const ulonglong2*>(&vals4[m * 16 + d4i]);
            v2a[m] = vv.x;
            v2b[m] = vv.y;
        }

        // H_time epilogue: 16 rows per thread, f32x2 packed, coalesced STG.128
        float4* oh = (float4*)outH + ((size_t)bo * N_ + n0) * 16;
        #pragma unroll 1
        for (int it = 0; it < 16; it++) {
            int row = it * 8 + rbase;
            ulonglong2 h2 = *reinterpret_cast<const ulonglong2*>(&Hs4[row * 17 + d4i]);
            const float4* arow = (const float4*)(attn_s + row * 12);
            float4 a0 = arow[0], a1 = arow[1], a2 = arow[2];
            float am[M_] = {a0.x, a0.y, a0.z, a0.w,
                            a1.x, a1.y, a1.z, a1.w,
                            a2.x, a2.y, a2.z, a2.w};
            u64 acca = 0ull, accb = 0ull;
            #pragma unroll
            for (int m = 0; m < M_; m++) {
                u64 s = splat2(am[m]);
                acca = ffma2(s, v2a[m], acca);
                accb = ffma2(s, v2b[m], accb);
            }
            ulonglong2 r;
            r.x = ffma2(alpha2, acca, h2.x);
            r.y = ffma2(alpha2, accb, h2.y);
            *reinterpret_cast<ulonglong2*>(&oh[(size_t)row * 16 + d4i]) = r;
        }
    }
}

// ---------------------------------------------------------------------------
extern "C" void kernel_launch(void* const* d_in, const int* in_sizes, int n_in,
                              void* d_out, int out_size)
{
    const float* H        = (const float*)d_in[0];
    const float* ts_out   = (const float*)d_in[1];
    const float* step_emb = (const float*)d_in[2];
    const float* key_emb  = (const float*)d_in[3];
    const float* val_emb  = (const float*)d_in[4];
    const float* Wk       = (const float*)d_in[5];
    const float* Wg       = (const float*)d_in[6];
    const float* bg       = (const float*)d_in[7];
    const float* Wq       = (const float*)d_in[8];
    const float* bq       = (const float*)d_in[9];

    float* out     = (float*)d_out;
    float* outH    = out;                                   // [B,O,N,D]
    float* outAttn = out + (size_t)B_ * O_ * N_ * D_;       // [B,O,N,M]
    float* outGate = outAttn + (size_t)B_ * O_ * N_ * M_;   // [B,O,M]

    prep_kernel<<<B_ * O_, 128>>>(ts_out, step_emb, key_emb, val_emb,
                                  Wk, Wg, bg, Wq, bq, outGate);

    const int smem = (NT * 17 + 512 + 96 + 192) * (int)sizeof(float4)
                   + (NT * 12 + 12) * (int)sizeof(float);   // 53,808 B
    cudaFuncSetAttribute(main_kernel, cudaFuncAttributeMaxDynamicSharedMemorySize, smem);
    dim3 grid(N_ / NT, B_);
    main_kernel<<<grid, NT, smem>>>(H, Wq, outH, outAttn);
}

// round 13
// speedup vs baseline: 1.0169x; 1.0165x over previous
#include <cuda_runtime.h>
#include <math.h>

// Problem constants
constexpr int B_ = 16, N_ = 4096, D_ = 64, O_ = 12, S_ = 32, M_ = 12, A_ = 32;
constexpr int NT = 128;                       // n-rows per block
constexpr float SCALE_ = 0.17677669529663687f; // 1/sqrt(A)
constexpr float ALPHA_ = 0.1f;
constexpr float TWO_PI = 6.283185307179586f;

using u64 = unsigned long long;

// ---- packed f32x2 helpers (sm_103a) ---------------------------------------
__device__ __forceinline__ u64 splat2(float x) {
    u64 r; asm("mov.b64 %0, {%1, %1};" : "=l"(r) : "f"(x)); return r;
}
__device__ __forceinline__ u64 pk2(float lo, float hi) {
    u64 r; asm("mov.b64 %0, {%1, %2};" : "=l"(r) : "f"(lo), "f"(hi)); return r;
}
__device__ __forceinline__ float2 unpk2(u64 v) {
    float2 f; asm("mov.b64 {%0, %1}, %2;" : "=f"(f.x), "=f"(f.y) : "l"(v)); return f;
}
__device__ __forceinline__ u64 ffma2(u64 a, u64 b, u64 c) {
    u64 d; asm("fma.rn.f32x2 %0, %1, %2, %3;" : "=l"(d) : "l"(a), "l"(b), "l"(c)); return d;
}

// Scratch (per (b,o) precomputed small tensors)
__device__ __align__(16) float g_keys[B_ * O_ * M_ * A_]; // [bo][m][a]  (pre-scaled by SCALE_)
__device__ __align__(16) float g_vals[B_ * O_ * M_ * D_]; // [bo][m][d]  (gated)
__device__ __align__(16) float g_qsk [B_ * O_ * M_];      // [bo][m] = qs . key_scaled[m]

// ---------------------------------------------------------------------------
// Prep: per (b,o) fourier tokens, gate (-> output), scaled keys, gated vals,
// folded scalar qsk[m] = (step_emb@WqS + bq) . (SCALE * key[m]).
// ---------------------------------------------------------------------------
__global__ void prep_kernel(const float* __restrict__ ts_out,
                            const float* __restrict__ step_emb,
                            const float* __restrict__ key_emb,
                            const float* __restrict__ val_emb,
                            const float* __restrict__ Wk,
                            const float* __restrict__ Wg,
                            const float* __restrict__ bg,
                            const float* __restrict__ Wq,
                            const float* __restrict__ bq,
                            float* __restrict__ out_gate)
{
    const int bo = blockIdx.x;
    const int t  = threadIdx.x;

    __shared__ float s_sin[M_], s_cos[M_], s_gate[M_], s_qs[A_], s_keys[M_ * A_];

    if (t < M_) {
        float phase = (t < 8) ? ts_out[bo * 2 + 0] : ts_out[bo * 2 + 1];
        int   k     = (t < 8) ? (t + 1) : (t - 7);
        float ang   = TWO_PI * phase * (float)k;
        float s, c;
        sincosf(ang, &s, &c);
        s_sin[t] = s;
        s_cos[t] = c;
        float gate = tanhf(fmaf(Wg[0], s, fmaf(Wg[1], c, bg[0])));
        s_gate[t] = gate;
        out_gate[bo * M_ + t] = gate;
    }
    if (t < A_) {
        float acc = bq[t];
        const float* se = step_emb + bo * S_;
        const float* w  = Wq + t * (D_ + S_) + D_;
        #pragma unroll
        for (int s = 0; s < S_; s++) acc = fmaf(se[s], w[s], acc);
        s_qs[t] = acc;
    }
    __syncthreads();

    // keys[m][a], pre-scaled by SCALE_
    for (int i = t; i < M_ * A_; i += blockDim.x) {
        int m = i / A_, a = i % A_;
        float v = fmaf(Wk[a * 2 + 0], s_sin[m], fmaf(Wk[a * 2 + 1], s_cos[m], key_emb[i]));
        v *= SCALE_;
        s_keys[i] = v;
        g_keys[bo * M_ * A_ + i] = v;
    }
    // gated vals[m][d]
    for (int i = t; i < M_ * D_; i += blockDim.x) {
        int m = i / D_;
        g_vals[bo * M_ * D_ + i] = s_gate[m] * val_emb[i];
    }
    __syncthreads();

    if (t < M_) {
        float acc = 0.f;
        #pragma unroll
        for (int a = 0; a < A_; a++) acc = fmaf(s_qs[a], s_keys[t * A_ + a], acc);
        g_qsk[bo * M_ + t] = acc;
    }
}

// ---------------------------------------------------------------------------
// Main: one block per (b, 128-row n-tile). qh computed once, reused for all O.
// f32x2 packed math throughout; vals hoisted to registers in the epilogue.
// ---------------------------------------------------------------------------
__global__ void __launch_bounds__(NT, 4)
main_kernel(const float* __restrict__ H,
            const float* __restrict__ Wq,
            float* __restrict__ outH,
            float* __restrict__ outAttn)
{
    extern __shared__ float4 sm4[];
    float4* Hs4   = sm4;               // [128][17] padded -> 2176 float4
    float4* Wq4   = Hs4 + NT * 17;     // [32][16]          -> 512
    float4* keys4 = Wq4 + 512;         // [12][8]           -> 96
    float4* vals4 = keys4 + 96;        // [12][16]          -> 192
    float*  attn_s = (float*)(vals4 + 192); // [128][12] contiguous (float4-friendly)
    float*  qsk_s  = attn_s + NT * 12;      // [12]

    const int t  = threadIdx.x;
    const int n0 = blockIdx.x * NT;
    const int b  = blockIdx.y;

    // Stage H tile (coalesced), padded stride 17 (conflict-free epilogue reads).
    const float4* Hg4 = (const float4*)(H + ((size_t)b * N_ + n0) * D_);
    for (int i = t; i < NT * 16; i += NT)
        Hs4[(i >> 4) * 17 + (i & 15)] = Hg4[i];

    // Stage Wq (first D columns) as [a][d4] float4.
    for (int i = t; i < A_ * 16; i += NT) {
        int a = i >> 4, d4 = i & 15;
        Wq4[i] = *(const float4*)(Wq + a * (D_ + S_) + d4 * 4);
    }
    __syncthreads();

    // qh[a] = H[row] . Wq[a,:D], accumulated over d-pairs with f32x2,
    // then reduced and repacked into a-pairs qh2[j] = (qh[2j], qh[2j+1]).
    u64 acc2[A_];
    #pragma unroll
    for (int a = 0; a < A_; a++) acc2[a] = 0ull;
    #pragma unroll 4
    for (int d4 = 0; d4 < 16; d4++) {
        ulonglong2 h2 = *reinterpret_cast<const ulonglong2*>(&Hs4[t * 17 + d4]);
        #pragma unroll
        for (int a = 0; a < A_; a++) {
            ulonglong2 w2 = *reinterpret_cast<const ulonglong2*>(&Wq4[a * 16 + d4]);
            acc2[a] = ffma2(h2.x, w2.x, acc2[a]);
            acc2[a] = ffma2(h2.y, w2.y, acc2[a]);
        }
    }
    u64 qh2[A_ / 2];
    #pragma unroll
    for (int j = 0; j < A_ / 2; j++) {
        float2 p = unpk2(acc2[2 * j]);
        float2 q = unpk2(acc2[2 * j + 1]);
        qh2[j] = pk2(p.x + p.y, q.x + q.y);
    }

    const int rbase = t >> 4;   // 0..7
    const int d4i   = t & 15;   // 0..15
    const u64 alpha2 = pk2(ALPHA_, ALPHA_);

    for (int o = 0; o < O_; o++) {
        const int bo = b * O_ + o;
        __syncthreads();  // previous iteration's readers of keys/vals/attn done

        const float4* gk4 = (const float4*)(g_keys + bo * M_ * A_);
        if (t < 96)  keys4[t] = gk4[t];
        const float4* gv4 = (const float4*)(g_vals + bo * M_ * D_);
        for (int i = t; i < 192; i += NT) vals4[i] = gv4[i];
        if (t < M_)  qsk_s[t] = g_qsk[bo * M_ + t];
        __syncthreads();

        // logits (f32x2 over a-pairs) + softmax in registers
        float lg[M_];
        #pragma unroll
        for (int m = 0; m < M_; m++) {
            u64 acc = 0ull;
            #pragma unroll
            for (int a4 = 0; a4 < 8; a4++) {
                ulonglong2 k2 = *reinterpret_cast<const ulonglong2*>(&keys4[m * 8 + a4]);
                acc = ffma2(qh2[2 * a4],     k2.x, acc);
                acc = ffma2(qh2[2 * a4 + 1], k2.y, acc);
            }
            float2 p = unpk2(acc);
            lg[m] = p.x + p.y + qsk_s[m];   // SCALE_ already folded into keys/qsk
        }
        float mx = lg[0];
        #pragma unroll
        for (int m = 1; m < M_; m++) mx = fmaxf(mx, lg[m]);
        float sum = 0.f;
        #pragma unroll
        for (int m = 0; m < M_; m++) { lg[m] = __expf(lg[m] - mx); sum += lg[m]; }
        float inv = 1.0f / sum;
        #pragma unroll
        for (int m = 0; m < M_; m++) lg[m] *= inv;

        // attn -> smem as 3 float4 (row stride 12 floats = 48B, 16B aligned)
        float4* arw = (float4*)(attn_s + t * 12);
        arw[0] = make_float4(lg[0], lg[1], lg[2],  lg[3]);
        arw[1] = make_float4(lg[4], lg[5], lg[6],  lg[7]);
        arw[2] = make_float4(lg[8], lg[9], lg[10], lg[11]);
        __syncthreads();

        // attn global write: smem layout == global layout -> straight float4 copy
        {
            float4* oa4 = (float4*)(outAttn + ((size_t)bo * N_ + n0) * M_);
            const float4* as4 = (const float4*)attn_s;
            #pragma unroll
            for (int k = 0; k < 3; k++) oa4[t + k * NT] = as4[t + k * NT];
        }

        // hoist this thread's gated vals (fixed d4i) into registers: 12 LDS.128
        u64 v2a[M_], v2b[M_];
        #pragma unroll
        for (int m = 0; m < M_; m++) {
            ulonglong2 vv = *reinterpret_cast<const ulonglong2*>(&vals4[m * 16 + d4i]);
            v2a[m] = vv.x;
            v2b[m] = vv.y;
        }

        // H_time epilogue: 16 rows per thread, f32x2 packed, coalesced STG.128
        float4* oh = (float4*)outH + ((size_t)bo * N_ + n0) * 16;
        #pragma unroll 1
        for (int it = 0; it < 16; it++) {
            int row = it * 8 + rbase;
            ulonglong2 h2 = *reinterpret_cast<const ulonglong2*>(&Hs4[row * 17 + d4i]);
            const float4* arow = (const float4*)(attn_s + row * 12);
            float4 a0 = arow[0], a1 = arow[1], a2 = arow[2];
            float am[M_] = {a0.x, a0.y, a0.z, a0.w,
                            a1.x, a1.y, a1.z, a1.w,
                            a2.x, a2.y, a2.z, a2.w};
            u64 acca = 0ull, accb = 0ull;
            #pragma unroll
            for (int m = 0; m < M_; m++) {
                u64 s = splat2(am[m]);
                acca = ffma2(s, v2a[m], acca);
                accb = ffma2(s, v2b[m], accb);
            }
            ulonglong2 r;
            r.x = ffma2(alpha2, acca, h2.x);
            r.y = ffma2(alpha2, accb, h2.y);
            *reinterpret_cast<ulonglong2*>(&oh[(size_t)row * 16 + d4i]) = r;
        }
    }
}

// ---------------------------------------------------------------------------
extern "C" void kernel_launch(void* const* d_in, const int* in_sizes, int n_in,
                              void* d_out, int out_size)
{
    const float* H        = (const float*)d_in[0];
    const float* ts_out   = (const float*)d_in[1];
    const float* step_emb = (const float*)d_in[2];
    const float* key_emb  = (const float*)d_in[3];
    const float* val_emb  = (const float*)d_in[4];
    const float* Wk       = (const float*)d_in[5];
    const float* Wg       = (const float*)d_in[6];
    const float* bg       = (const float*)d_in[7];
    const float* Wq       = (const float*)d_in[8];
    const float* bq       = (const float*)d_in[9];

    float* out     = (float*)d_out;
    float* outH    = out;                                   // [B,O,N,D]
    float* outAttn = out + (size_t)B_ * O_ * N_ * D_;       // [B,O,N,M]
    float* outGate = outAttn + (size_t)B_ * O_ * N_ * M_;   // [B,O,M]

    prep_kernel<<<B_ * O_, 128>>>(ts_out, step_emb, key_emb, val_emb,
                                  Wk, Wg, bg, Wq, bq, outGate);

    const int smem = (NT * 17 + 512 + 96 + 192) * (int)sizeof(float4)
                   + (NT * 12 + 12) * (int)sizeof(float);   // 53,808 B
    cudaFuncSetAttribute(main_kernel, cudaFuncAttributeMaxDynamicSharedMemorySize, smem);
    dim3 grid(N_ / NT, B_);
    main_kernel<<<grid, NT, smem>>>(H, Wq, outH, outAttn);
}